// round 17
// baseline (speedup 1.0000x reference)
#include <cuda_runtime.h>
#include <cuda_bf16.h>
#include <cstdint>

#define Wd 960
#define Hd 544
#define Td 64
#define PAD 100
#define KSZ 201

#define CH 17                    // window chunks (k16 each)
#define PAe 280                  // window pitch (elements); 560B rows conflict-free
#define WINB (128 * PAe * 2)     // 71680
#define SMB  WINB                // B tiles offset
#define BTB  (14 * 16 * 24 * 2)  // 10752 (14 tiles, 16 rows x 48B)
#define TRO  (SMB + BTB)         // 82432 (16B aligned)
#define TP1 136                  // p1 transpose pitch (bf16): 272B rows, 16B-aligned
#define TP2 130                  // p2 transpose pitch (f32): 520B rows, 8B-aligned only
#define P1_SMEM (TRO + 64 * TP1 * 2)   // 99840
#define P2_SMEM (TRO + 64 * TP2 * 4)   // 115712 (occ-2 ceiling incl. reserve)
#define NT 512

__device__ __nv_bfloat16 g_mid[(size_t)Td * Wd * Hd];   // [t][c][h]

// ---------------- constexpr Gaussian weights -> __constant__ table ----------
__host__ __device__ constexpr double cexp(double x) {
    int n = (int)(x * 1.4426950408889634 - 0.5);   // x <= 0
    double r = x - (double)n * 0.69314718055994530941723212;
    double term = 1.0, p = 1.0;
    for (int k = 1; k <= 16; k++) { term *= r / (double)k; p += term; }
    double s = 1.0;
    for (int i = 0; i < -n; i++) s *= 0.5;
    return p * s;
}
struct GK { float v[KSZ]; };
__host__ __device__ constexpr GK make_gk() {
    GK g{};
    for (int i = 0; i < KSZ; i++) {
        double r = (double)(i - PAD);
        g.v[i] = (float)(cexp(-(r * r) / (2.0 * 25.0 * 25.0)) / 62.665706865775006);
    }
    return g;
}
__constant__ GK c_gk = make_gk();

// ---------------- PTX helpers ------------------------------------------------
__device__ __forceinline__ uint32_t smem_u32(const void* p) {
    uint32_t a;
    asm("{ .reg .u64 t; cvta.to.shared.u64 t, %1; cvt.u32.u64 %0, t; }"
        : "=r"(a) : "l"(p));
    return a;
}
__device__ __forceinline__ void ldsm4(uint32_t& r0, uint32_t& r1, uint32_t& r2,
                                      uint32_t& r3, uint32_t a) {
    asm volatile("ldmatrix.sync.aligned.m8n8.x4.shared.b16 {%0,%1,%2,%3}, [%4];"
        : "=r"(r0), "=r"(r1), "=r"(r2), "=r"(r3) : "r"(a));
}
__device__ __forceinline__ void stsm4t(uint32_t a, uint32_t r0, uint32_t r1,
                                       uint32_t r2, uint32_t r3) {
    asm volatile("stmatrix.sync.aligned.m8n8.x4.trans.shared.b16 [%0], {%1,%2,%3,%4};"
        :: "r"(a), "r"(r0), "r"(r1), "r"(r2), "r"(r3) : "memory");
}
__device__ __forceinline__ uint32_t packbf(float lo, float hi) {
    uint32_t r;
    asm("cvt.rn.satfinite.bf16x2.f32 %0, %1, %2;" : "=r"(r) : "f"(hi), "f"(lo));
    return r;
}
__device__ __forceinline__ void mma16816(float* d, uint32_t a0, uint32_t a1,
                                         uint32_t a2, uint32_t a3,
                                         uint32_t b0, uint32_t b1) {
    asm volatile("mma.sync.aligned.m16n8k16.row.col.f32.bf16.bf16.f32 "
        "{%0,%1,%2,%3}, {%4,%5,%6,%7}, {%8,%9}, {%0,%1,%2,%3};"
        : "+f"(d[0]), "+f"(d[1]), "+f"(d[2]), "+f"(d[3])
        : "r"(a0), "r"(a1), "r"(a2), "r"(a3), "r"(b0), "r"(b1));
}

// ---------------- staging helpers (8 cols, 4-col guard granularity) ---------
__device__ __forceinline__ void stage8f(const float* src, int gc, void* dst) {
    float4 a = {0.f, 0.f, 0.f, 0.f}, b = {0.f, 0.f, 0.f, 0.f};
    if (gc >= 0 && gc + 3 < Wd)     a = *(const float4*)(src);
    if (gc + 4 >= 0 && gc + 7 < Wd) b = *(const float4*)(src + 4);
    __nv_bfloat162 q0 = __floats2bfloat162_rn(a.x, a.y);
    __nv_bfloat162 q1 = __floats2bfloat162_rn(a.z, a.w);
    __nv_bfloat162 q2 = __floats2bfloat162_rn(b.x, b.y);
    __nv_bfloat162 q3 = __floats2bfloat162_rn(b.z, b.w);
    uint4 w = { *(uint32_t*)&q0, *(uint32_t*)&q1, *(uint32_t*)&q2, *(uint32_t*)&q3 };
    *(uint4*)dst = w;
}
__device__ __forceinline__ void stage8h(const __nv_bfloat16* src, int gh, void* dst) {
    uint2 w0 = {0u, 0u}, w1 = {0u, 0u};
    if (gh >= 0 && gh + 3 < Hd)     w0 = *(const uint2*)(src);
    if (gh + 4 >= 0 && gh + 7 < Hd) w1 = *(const uint2*)(src + 4);
    uint4 w = {w0.x, w0.y, w1.x, w1.y};
    *(uint4*)dst = w;
}

// ---------------- inline B-tile build (once per CTA) ------------------------
__device__ __forceinline__ void build_btiles(char* smc, int tid) {
    for (int i = tid; i < 14 * 16 * 24; i += NT) {
        int e = i / 384, r = (i / 24) & 15, k = i % 24;
        int t = 16 * e + k - r;
        float v = (k < 16 && t >= 0 && t < KSZ) ? c_gk.v[t] : 0.0f;
        ((__nv_bfloat16*)(smc + SMB))[i] = __float2bfloat16(v);
    }
}

// ---------------- per-step MMA: relative-B band loop ------------------------
// Chunk i in window (abs q = 4s+i). Warp half HH covers 16-col tiles 2HH (acc0/1)
// and 2HH+1 (acc2/3); tile index e = i - T, valid iff e in [0,13].
template<int HH>
__device__ __forceinline__ void step_mma(uint32_t aBase, uint32_t bBase,
                                         int s4, float acc[4][4]) {
#pragma unroll
    for (int i = 0; i < CH; i++) {
        const int  e0 = i - 2 * HH;
        const int  e1 = e0 - 1;
        const bool v0 = (e0 >= 0) && (e0 <= 13);
        const bool v1 = (e1 >= 0) && (e1 <= 13);
        if (!(v0 || v1)) continue;
        int slot = s4 + i; if (slot >= CH) slot -= CH;
        uint32_t a0, a1, a2, a3;
        ldsm4(a0, a1, a2, a3, aBase + slot * 32);
        if (v0) {
            uint32_t b0, b1, b2, b3;
            ldsm4(b0, b1, b2, b3, bBase + e0 * 768);
            mma16816(acc[0], a0, a1, a2, a3, b0, b1);
            mma16816(acc[1], a0, a1, a2, a3, b2, b3);
        }
        if (v1) {
            uint32_t b0, b1, b2, b3;
            ldsm4(b0, b1, b2, b3, bBase + e1 * 768);
            mma16816(acc[2], a0, a1, a2, a3, b0, b1);
            mma16816(acc[3], a0, a1, a2, a3, b2, b3);
        }
    }
}

// ====================== Pass 1: persistent row-strip, blur along W ==========
__global__ void __launch_bounds__(NT, 2) p1(const float* __restrict__ x) {
    extern __shared__ char smc[];
    uint32_t sb = smem_u32(smc);
    const int tid = threadIdx.x;
    const int wid = tid >> 5, lid = tid & 31;
    const int wm = wid & 7, hh = wid >> 3;
    const int row0 = blockIdx.x * 128;           // flat (t*Hd + h)

    build_btiles(smc, tid);
    // initial window: chunks 0..16 = input cols [-100, 172)
    for (int i = tid; i < 128 * 34; i += NT) {
        int r = i / 34, j = i % 34;
        int gc = j * 8 - PAD;
        stage8f(x + (size_t)(row0 + r) * Wd + gc, gc,
                smc + ((size_t)r * PAe + j * 8) * 2);
    }
    __syncthreads();

    const int mi = lid >> 3, lrow = lid & 7;
    const uint32_t aBase = sb +
        (((wm * 16) + ((mi & 1) << 3) + lrow) * PAe + ((mi >> 1) << 3)) * 2;
    const uint32_t bBase = sb + SMB + ((((mi >> 1) << 3) + lrow) * 48 + (mi & 1) * 16);

    // stmatrix.trans epilogue addresses (step-invariant):
    // tile t = lid>>3, row-in-tile i = lid&7; block = 4*hh + nb2 + (t>>1);
    // c = block*8 + i, m0 = wm*16 + (t&1)*8; addr = TRO + (c*TP1 + m0)*2
    const int st_t = lid >> 3, st_i = lid & 7;
    const uint32_t trA = sb + TRO +
        (((4 * hh + (st_t >> 1)) * 8 + st_i) * TP1 + wm * 16 + (st_t & 1) * 8) * 2;
    const uint32_t trB = trA + 16 * TP1 * 2;     // blocks +2

    const int t0g = row0 / Hd, h0g = row0 % Hd;  // h0g multiple of 32
    const int rem = Hd - h0g;
    const int len1 = (128 < rem) ? 128 : rem;

    int s4 = 0;
    for (int s = 0; s < 15; s++) {
        float acc[4][4];
#pragma unroll
        for (int nb = 0; nb < 4; nb++)
#pragma unroll
            for (int k = 0; k < 4; k++) acc[nb][k] = 0.f;

        if (hh == 0) step_mma<0>(aBase, bBase, s4, acc);
        else         step_mma<1>(aBase, bBase, s4, acc);
        __syncthreads();                          // window + prev tr reads done

        // epilogue -> bf16 transpose buffer via stmatrix.trans
        stsm4t(trA, packbf(acc[0][0], acc[0][1]), packbf(acc[0][2], acc[0][3]),
                    packbf(acc[1][0], acc[1][1]), packbf(acc[1][2], acc[1][3]));
        stsm4t(trB, packbf(acc[2][0], acc[2][1]), packbf(acc[2][2], acc[2][3]),
                    packbf(acc[3][0], acc[3][1]), packbf(acc[3][2], acc[3][3]));

        // stage next 4 chunks (q = 4s+17 .. 4s+20) into retired slots
        if (s < 14) {
            int cstart = 64 * s + 172;            // 16*(4s+17) - 100
#pragma unroll
            for (int it = 0; it < 2; it++) {
                int id = tid + it * NT;
                int r = id >> 3, hc = id & 7;
                int slot = s4 + (hc >> 1); if (slot >= CH) slot -= CH;
                int gc = cstart + hc * 8;
                stage8f(x + (size_t)(row0 + r) * Wd + gc, gc,
                        smc + ((size_t)r * PAe + slot * 16 + (hc & 1) * 8) * 2);
            }
        }
        __syncthreads();                          // tr + staged visible

        // coalesced store to g_mid[t][c][h]
        const int c0 = s * 64;
        const __nv_bfloat16* tr = (const __nv_bfloat16*)(smc + TRO);
        for (int idx = tid; idx < 64 * 32; idx += NT) {
            int c = idx >> 5, m = (idx & 31) * 4;
            uint2 w = *(const uint2*)(tr + c * TP1 + m);
            int t = t0g, hcol = h0g + m;
            if (m >= len1) { t = t0g + 1; hcol = m - len1; }
            *(uint2*)(&g_mid[((size_t)t * Wd + (c0 + c)) * Hd + hcol]) = w;
        }
        s4 += 4; if (s4 >= CH) s4 -= CH;
    }
}

// ====================== Pass 2: persistent row-strip, blur along H ==========
__global__ void __launch_bounds__(NT, 2) p2(float* __restrict__ out) {
    extern __shared__ char smc[];
    uint32_t sb = smem_u32(smc);
    const int tid = threadIdx.x;
    const int wid = tid >> 5, lid = tid & 31;
    const int wm = wid & 7, hh = wid >> 3;
    const int row0 = blockIdx.x * 128;           // flat (t*Wd + c)

    build_btiles(smc, tid);
    for (int i = tid; i < 128 * 34; i += NT) {
        int r = i / 34, j = i % 34;
        int gh = j * 8 - PAD;
        stage8h(g_mid + (size_t)(row0 + r) * Hd + gh, gh,
                smc + ((size_t)r * PAe + j * 8) * 2);
    }
    __syncthreads();

    const int mi = lid >> 3, lrow = lid & 7;
    const uint32_t aBase = sb +
        (((wm * 16) + ((mi & 1) << 3) + lrow) * PAe + ((mi >> 1) << 3)) * 2;
    const uint32_t bBase = sb + SMB + ((((mi >> 1) << 3) + lrow) * 48 + (mi & 1) * 16);

    const int t0g = row0 / Wd, cst = row0 % Wd;  // cst multiple of 64
    const int rem = Wd - cst;
    const int len1 = (128 < rem) ? 128 : rem;    // multiple of 64

    int s4 = 0;
    for (int s = 0; s < 9; s++) {                // 8 full steps + 32-col tail
        const bool full = (s < 8);
        float acc[4][4];
#pragma unroll
        for (int nb = 0; nb < 4; nb++)
#pragma unroll
            for (int k = 0; k < 4; k++) acc[nb][k] = 0.f;

        if (hh == 0)   step_mma<0>(aBase, bBase, s4, acc);
        else if (full) step_mma<1>(aBase, bBase, s4, acc);
        __syncthreads();

        if (hh == 0 || full) {
            const int g = lid >> 2, i2 = (lid & 3) * 2;
            const int mrow = wm * 16 + g;
            float* tr = (float*)(smc + TRO);
#pragma unroll
            for (int nb = 0; nb < 4; nb++) {
                int c = (4 * hh + nb) * 8 + i2;
                tr[c * TP2 + mrow]           = acc[nb][0];
                tr[(c + 1) * TP2 + mrow]     = acc[nb][1];
                tr[c * TP2 + mrow + 8]       = acc[nb][2];
                tr[(c + 1) * TP2 + mrow + 8] = acc[nb][3];
            }
        }
        if (full) {                               // stage q = 4s+17..4s+20, q <= 46
            int cstart = 64 * s + 172;
#pragma unroll
            for (int it = 0; it < 2; it++) {
                int id = tid + it * NT;
                int r = id >> 3, hc = id & 7;
                int q = 4 * s + 17 + (hc >> 1);
                if (q <= 46) {
                    int slot = s4 + (hc >> 1); if (slot >= CH) slot -= CH;
                    int gh = cstart + hc * 8;
                    stage8h(g_mid + (size_t)(row0 + r) * Hd + gh, gh,
                            smc + ((size_t)r * PAe + slot * 16 + (hc & 1) * 8) * 2);
                }
            }
        }
        __syncthreads();

        // store: float2 pairs (TP2=130 rows are 8B-aligned, NOT 16B)
        const int h0o = s * 64;
        const int ncols = full ? 64 : 32;
        const float* tr = (const float*)(smc + TRO);
        for (int idx = tid; idx < ncols * 32; idx += NT) {
            int n = idx >> 5, m = (idx & 31) * 4;
            float2 w01 = *(const float2*)(tr + n * TP2 + m);
            float2 w23 = *(const float2*)(tr + n * TP2 + m + 2);
            int t = t0g, c = cst + m;
            if (m >= len1) { t = t0g + 1; c = m - len1; }
            float* dst = &out[((size_t)t * Hd + (h0o + n)) * Wd + c];
            *(float2*)(dst)     = w01;
            *(float2*)(dst + 2) = w23;
        }
        s4 += 4; if (s4 >= CH) s4 -= CH;
    }
}

// ====================== launch ==============================================
extern "C" void kernel_launch(void* const* d_in, const int* in_sizes, int n_in,
                              void* d_out, int out_size) {
    const float* x = (const float*)d_in[0];
    float* out = (float*)d_out;

    cudaFuncSetAttribute(p1, cudaFuncAttributeMaxDynamicSharedMemorySize, P1_SMEM);
    cudaFuncSetAttribute(p2, cudaFuncAttributeMaxDynamicSharedMemorySize, P2_SMEM);

    p1<<<(Td * Hd) / 128, NT, P1_SMEM>>>(x);     // 272 CTAs
    p2<<<(Td * Wd) / 128, NT, P2_SMEM>>>(out);   // 480 CTAs
}